// round 2
// baseline (speedup 1.0000x reference)
#include <cuda_runtime.h>
#include <math.h>

#define Bsz 32
#define Cc 64
#define Hh 256
#define Ww 256
#define HIDN 128
#define NEG_FILL -1.0e9f

// ---- scratch (no allocations allowed) ----
__device__ float g_att[Bsz * Hh * Ww];
__device__ float g_max[Bsz];
__device__ float g_sumE[Bsz];
__device__ float g_sumPE[Bsz];
__device__ int   g_cnt[Bsz];

__device__ __forceinline__ void atomicMaxF(float* addr, float val) {
    int* ai = (int*)addr;
    int old = *ai;
    while (__int_as_float(old) < val) {
        int assumed = old;
        old = atomicCAS(ai, assumed, __float_as_int(val));
        if (old == assumed) break;
    }
}

__global__ void k_init() {
    int t = threadIdx.x;
    if (t < Bsz) {
        g_max[t]   = -3.0e38f;
        g_sumE[t]  = 0.0f;
        g_sumPE[t] = 0.0f;
        g_cnt[t]   = 0;
    }
}

// One block per (batch, row). Compact masked columns, gather features into SMEM,
// cooperative 128-wide hidden layer with W1 rows register-resident.
__global__ void k_scores(const float* __restrict__ feat,
                         const int*   __restrict__ zone,
                         const int*   __restrict__ cats,
                         const float* __restrict__ W1,
                         const float* __restrict__ b1,
                         const float* __restrict__ W2,
                         const float* __restrict__ b2p) {
    const int h = blockIdx.x, b = blockIdx.y;
    const int tid  = threadIdx.x;
    const int lane = tid & 31, warp = tid >> 5;

    __shared__ __align__(16) float s_f[64][66];  // 16B-aligned: LDS.64 broadcast reads
    __shared__ int   s_list[256];
    __shared__ float s_score[256];
    __shared__ int   s_wcnt[8];
    __shared__ int   s_m;
    __shared__ float s_maxp[8];

    const int cat = __ldg(&cats[b]);
    const int rowbase = (b * Hh + h) * Ww;
    const int z = zone[rowbase + tid];
    const bool masked = (z == cat);           // cat >= 1 so z>0 is implied

    unsigned ball = __ballot_sync(0xffffffffu, masked);
    if (lane == 0) s_wcnt[warp] = __popc(ball);
    s_score[tid] = 0.0f;
    __syncthreads();
    if (tid == 0) {
        int acc = 0;
#pragma unroll
        for (int i = 0; i < 8; i++) { int t = s_wcnt[i]; s_wcnt[i] = acc; acc += t; }
        s_m = acc;
    }
    __syncthreads();
    const int m = s_m;
    int myidx = -1;
    if (masked) {
        myidx = s_wcnt[warp] + __popc(ball & ((1u << lane) - 1u));
        s_list[myidx] = tid;
    }

    // Each thread owns hidden unit k = tid & 127 (two groups share k, split pixels).
    const int k = tid & 127;
    float w1r[64];
#pragma unroll
    for (int c = 0; c < 64; c++) w1r[c] = __ldg(&W1[k * 64 + c]);
    const float b1r = __ldg(&b1[k]);
    const float w2r = __ldg(&W2[k]);
    const int g = tid >> 7;                 // pixel group 0/1 (warp-uniform)
    const int fbase = b * (Cc * Hh * Ww) + h * Ww;

    for (int j0 = 0; j0 < m; j0 += 64) {
        const int mc = min(64, m - j0);
        __syncthreads();
        // gather features for this chunk: s_f[c][j]
        for (int i = tid; i < 64 * mc; i += 256) {
            int c = i / mc;
            int j = i - c * mc;
            int ww = s_list[j0 + j];
            s_f[c][j] = __ldg(&feat[fbase + c * (Hh * Ww) + ww]);
        }
        __syncthreads();
        // pixel pairs: group 0 -> pairs 0,2,4..., group 1 -> pairs 1,3,5...
        for (int p = g; 2 * p < mc; p += 2) {
            int j = 2 * p;
            float acc0 = b1r, acc1 = b1r;
#pragma unroll
            for (int c = 0; c < 64; c++) {
                float2 f2 = *(const float2*)&s_f[c][j];   // broadcast across warp
                acc0 = fmaf(w1r[c], f2.x, acc0);
                acc1 = fmaf(w1r[c], f2.y, acc1);
            }
            float v0 = fmaxf(acc0, 0.0f) * w2r;
            float v1 = fmaxf(acc1, 0.0f) * w2r;
#pragma unroll
            for (int off = 16; off; off >>= 1) {
                v0 += __shfl_xor_sync(0xffffffffu, v0, off);
                v1 += __shfl_xor_sync(0xffffffffu, v1, off);
            }
            if (lane == 0) {
                atomicAdd(&s_score[j0 + j], v0);
                if (j + 1 < mc) atomicAdd(&s_score[j0 + j + 1], v1);
            }
        }
    }
    __syncthreads();

    const float b2v = __ldg(b2p);
    float att = masked ? (s_score[myidx] + b2v) : NEG_FILL;
    g_att[rowbase + tid] = att;

    // block max over masked scores -> per-batch max
    float mv = masked ? att : -3.0e38f;
#pragma unroll
    for (int off = 16; off; off >>= 1)
        mv = fmaxf(mv, __shfl_xor_sync(0xffffffffu, mv, off));
    if (lane == 0) s_maxp[warp] = mv;
    __syncthreads();
    if (tid == 0) {
        float bm = s_maxp[0];
#pragma unroll
        for (int i = 1; i < 8; i++) bm = fmaxf(bm, s_maxp[i]);
        if (m > 0) {
            atomicMaxF(&g_max[b], bm);
            atomicAdd(&g_cnt[b], m);
        }
    }
}

__global__ void k_sums(const float* __restrict__ pl,
                       const int*   __restrict__ zone,
                       const int*   __restrict__ cats) {
    const int h = blockIdx.x, b = blockIdx.y, tid = threadIdx.x;
    const int lane = tid & 31, warp = tid >> 5;
    const int idx = (b * Hh + h) * Ww + tid;
    const int cat = __ldg(&cats[b]);
    float e = 0.0f, pe = 0.0f;
    if (zone[idx] == cat) {
        float att = g_att[idx];
        e  = expf(att - g_max[b]);
        pe = e * pl[idx];
    }
    __shared__ float se[8], sp[8];
#pragma unroll
    for (int off = 16; off; off >>= 1) {
        e  += __shfl_xor_sync(0xffffffffu, e,  off);
        pe += __shfl_xor_sync(0xffffffffu, pe, off);
    }
    if (lane == 0) { se[warp] = e; sp[warp] = pe; }
    __syncthreads();
    if (tid == 0) {
        float E = 0.0f, P = 0.0f;
#pragma unroll
        for (int i = 0; i < 8; i++) { E += se[i]; P += sp[i]; }
        if (E != 0.0f || P != 0.0f) {
            atomicAdd(&g_sumE[b],  E);
            atomicAdd(&g_sumPE[b], P);
        }
    }
}

__global__ void k_maps(const int* __restrict__ zone,
                       const int* __restrict__ cats,
                       float* __restrict__ out_maps) {
    const int h = blockIdx.x, b = blockIdx.y, tid = threadIdx.x;
    const int idx = (b * Hh + h) * Ww + tid;
    float w = 0.0f;
    if (g_cnt[b] > 0) {
        if (zone[idx] == __ldg(&cats[b])) {
            w = expf(g_att[idx] - g_max[b]) / g_sumE[b];
        }
    }
    out_maps[idx] = w;
}

__global__ void k_loss(const float* __restrict__ labels,
                       float* __restrict__ out, int write_loss) {
    const int t = threadIdx.x;   // 32 threads
    float x = 0.0f;
    if (g_cnt[t] > 0) x = g_sumPE[t] / g_sumE[t];
    float y = labels[t];
    float term = fmaxf(x, 0.0f) - x * y + log1pf(expf(-fabsf(x)));
#pragma unroll
    for (int off = 16; off; off >>= 1)
        term += __shfl_xor_sync(0xffffffffu, term, off);
    if (t == 0 && write_loss) out[0] = term / 32.0f;
}

extern "C" void kernel_launch(void* const* d_in, const int* in_sizes, int n_in,
                              void* d_out, int out_size) {
    const float* pl     = (const float*)d_in[0];  // (B,1,H,W)
    const float* feat   = (const float*)d_in[1];  // (B,C,H,W)
    const int*   zone   = (const int*)  d_in[2];  // (B,H,W)
    const int*   cats   = (const int*)  d_in[3];  // (B,)
    const float* labels = (const float*)d_in[4];  // (B,)
    const float* W1     = (const float*)d_in[5];  // (128,64)
    const float* b1     = (const float*)d_in[6];  // (128,)
    const float* W2     = (const float*)d_in[7];  // (128,)
    const float* b2     = (const float*)d_in[8];  // ()
    float* out = (float*)d_out;

    const int nmap = Bsz * Hh * Ww;
    int map_off = out_size - nmap;
    if (map_off < 0) map_off = 0;   // maps-only layout fallback

    dim3 grid(Hh, Bsz);
    k_init<<<1, 32>>>();
    k_scores<<<grid, 256>>>(feat, zone, cats, W1, b1, W2, b2);
    k_sums<<<grid, 256>>>(pl, zone, cats);
    k_maps<<<grid, 256>>>(zone, cats, out + map_off);
    k_loss<<<1, 32>>>(labels, out, map_off >= 1 ? 1 : 0);
}

// round 3
// speedup vs baseline: 3.3602x; 3.3602x over previous
#include <cuda_runtime.h>
#include <math.h>

#define Bsz 32
#define HW 65536          // H*W = 256*256
#define NPIX (Bsz * HW)
#define NBLK_MLP 592

// ---- scratch (no allocations allowed) ----
__device__ float g_e[NPIX];       // exp(score) at masked pixels (others stale/unused)
__device__ int   g_list[NPIX];    // compacted full pixel indices
__device__ int   g_total;
__device__ int   g_cnt[Bsz];
__device__ float g_sumE[Bsz];
__device__ float g_sumPE[Bsz];

__global__ void k_init() {
    int t = threadIdx.x;
    if (t < Bsz) { g_cnt[t] = 0; g_sumE[t] = 0.0f; g_sumPE[t] = 0.0f; }
    if (t == 0) g_total = 0;
}

// Grid: 8192 blocks x 256 threads; block = one (b,row), so b is warp-uniform.
__global__ void k_compact(const int* __restrict__ zone,
                          const int* __restrict__ cats) {
    const int idx  = blockIdx.x * 256 + threadIdx.x;
    const int b    = idx >> 16;
    const int lane = threadIdx.x & 31;
    const bool m   = (zone[idx] == __ldg(&cats[b]));   // cats>=1 so zone>0 implied
    unsigned ball  = __ballot_sync(0xffffffffu, m);
    int pos = 0;
    if (lane == 0 && ball) {
        int n = __popc(ball);
        pos = atomicAdd(&g_total, n);
        atomicAdd(&g_cnt[b], n);
    }
    pos = __shfl_sync(0xffffffffu, pos, 0);
    if (m) g_list[pos + __popc(ball & ((1u << lane) - 1u))] = idx;
}

// Persistent MLP over compacted pixels. One pixel per thread, features in
// registers, W1 broadcast from SMEM (conflict-free, LDS.128-friendly).
__global__ void __launch_bounds__(256) k_mlp(const float* __restrict__ feat,
                                             const float* __restrict__ pl,
                                             const float* __restrict__ W1,
                                             const float* __restrict__ b1,
                                             const float* __restrict__ W2,
                                             const float* __restrict__ b2p) {
    __shared__ __align__(16) float sW1[128 * 64];
    __shared__ float sB1[128], sW2[128];
    const int tid = threadIdx.x;

    // coalesced W1 -> smem (8 float4 per thread)
    for (int i = tid * 4; i < 128 * 64; i += 256 * 4)
        *(float4*)&sW1[i] = *(const float4*)&W1[i];
    if (tid < 128) { sB1[tid] = __ldg(&b1[tid]); sW2[tid] = __ldg(&W2[tid]); }
    __syncthreads();

    const int   total = g_total;
    const float b2    = __ldg(b2p);

    for (int base = blockIdx.x * 256; base < total; base += NBLK_MLP * 256) {
        const int i  = base + tid;
        const int fi = (i < total) ? g_list[i] : -1;

        float f[64];
        if (fi >= 0) {
            const int b = fi >> 16;
            const int p = fi & 65535;
            const float* fp = feat + ((size_t)b << 22) + p;   // b*64*65536
#pragma unroll
            for (int c = 0; c < 64; c++) f[c] = __ldg(fp + (c << 16));
        } else {
#pragma unroll
            for (int c = 0; c < 64; c++) f[c] = 0.0f;
        }

        float score = b2;
#pragma unroll 2
        for (int k = 0; k < 128; k++) {
            float h = sB1[k];
            const float* w = &sW1[k * 64];
#pragma unroll
            for (int c = 0; c < 64; c++) h = fmaf(w[c], f[c], h);
            score = fmaf(sW2[k], fmaxf(h, 0.0f), score);
        }

        if (fi >= 0) {
            const float e = expf(score);   // no max-sub: |score| is O(1), safe in fp32
            g_e[fi] = e;
            const int b = fi >> 16;
            atomicAdd(&g_sumE[b],  e);
            atomicAdd(&g_sumPE[b], e * __ldg(&pl[fi]));
        }
    }
}

__global__ void k_maps(const int* __restrict__ zone,
                       const int* __restrict__ cats,
                       float* __restrict__ out_maps) {
    const int idx = blockIdx.x * 256 + threadIdx.x;
    const int b   = idx >> 16;
    const float inv = 1.0f / g_sumE[b];          // block-uniform
    float w = 0.0f;
    if (g_cnt[b] > 0 && zone[idx] == __ldg(&cats[b]))
        w = g_e[idx] * inv;
    out_maps[idx] = w;
}

__global__ void k_loss(const float* __restrict__ labels,
                       float* __restrict__ out, int write_loss) {
    const int t = threadIdx.x;   // 32 threads
    float x = 0.0f;
    if (g_cnt[t] > 0) x = g_sumPE[t] / g_sumE[t];
    const float y = labels[t];
    float term = fmaxf(x, 0.0f) - x * y + log1pf(expf(-fabsf(x)));
#pragma unroll
    for (int off = 16; off; off >>= 1)
        term += __shfl_xor_sync(0xffffffffu, term, off);
    if (t == 0 && write_loss) out[0] = term / 32.0f;
}

extern "C" void kernel_launch(void* const* d_in, const int* in_sizes, int n_in,
                              void* d_out, int out_size) {
    const float* pl     = (const float*)d_in[0];  // (B,1,H,W)
    const float* feat   = (const float*)d_in[1];  // (B,C,H,W)
    const int*   zone   = (const int*)  d_in[2];  // (B,H,W)
    const int*   cats   = (const int*)  d_in[3];  // (B,)
    const float* labels = (const float*)d_in[4];  // (B,)
    const float* W1     = (const float*)d_in[5];  // (128,64)
    const float* b1     = (const float*)d_in[6];  // (128,)
    const float* W2     = (const float*)d_in[7];  // (128,)
    const float* b2     = (const float*)d_in[8];  // ()
    float* out = (float*)d_out;

    const int nmap = NPIX;
    int map_off = out_size - nmap;
    if (map_off < 0) map_off = 0;

    k_init<<<1, 32>>>();
    k_compact<<<NPIX / 256, 256>>>(zone, cats);
    k_mlp<<<NBLK_MLP, 256>>>(feat, pl, W1, b1, W2, b2);
    k_maps<<<NPIX / 256, 256>>>(zone, cats, out + map_off);
    k_loss<<<1, 32>>>(labels, out, map_off >= 1 ? 1 : 0);
}

// round 5
// speedup vs baseline: 3.5926x; 1.0691x over previous
#include <cuda_runtime.h>
#include <math.h>
#include <stdint.h>

#define Bsz 32
#define HW 65536          // H*W = 256*256
#define NPIX (Bsz * HW)
#define NBLK_MLP 592

// ---- scratch (no allocations allowed) ----
__device__ float g_e[NPIX];       // exp(score) at masked pixels (others stale/unused)
__device__ int   g_list[NPIX];    // compacted full pixel indices
__device__ int   g_total;
__device__ int   g_cnt[Bsz];
__device__ float g_sumE[Bsz];
__device__ float g_sumPE[Bsz];

#define FMA_F32X2(d, a, b, c) \
    asm("fma.rn.f32x2 %0, %1, %2, %3;" : "=l"(d) : "l"(a), "l"(b), "l"(c))
#define PACK_F32X2(out, lo, hi) \
    asm("mov.b64 %0, {%1, %2};" : "=l"(out) : "r"(lo), "r"(hi))
#define UNPACK_F32X2(lo, hi, in) \
    asm("mov.b64 {%0, %1}, %2;" : "=r"(lo), "=r"(hi) : "l"(in))

__global__ void k_init() {
    int t = threadIdx.x;
    if (t < Bsz) { g_cnt[t] = 0; g_sumE[t] = 0.0f; g_sumPE[t] = 0.0f; }
    if (t == 0) g_total = 0;
}

// Grid: 8192 blocks x 256 threads; block = one (b,row), so b is warp-uniform.
__global__ void k_compact(const int* __restrict__ zone,
                          const int* __restrict__ cats) {
    const int idx  = blockIdx.x * 256 + threadIdx.x;
    const int b    = idx >> 16;
    const int lane = threadIdx.x & 31;
    const bool m   = (zone[idx] == __ldg(&cats[b]));   // cats>=1 so zone>0 implied
    unsigned ball  = __ballot_sync(0xffffffffu, m);
    int pos = 0;
    if (lane == 0 && ball) {
        int n = __popc(ball);
        pos = atomicAdd(&g_total, n);
        atomicAdd(&g_cnt[b], n);
    }
    pos = __shfl_sync(0xffffffffu, pos, 0);
    if (m) g_list[pos + __popc(ball & ((1u << lane) - 1u))] = idx;
}

// Persistent MLP over compacted pixels. One pixel per thread; channels packed
// pairwise into f32x2; W1 pairs broadcast from SMEM via LDS.128.
__global__ void __launch_bounds__(256) k_mlp(const float* __restrict__ feat,
                                             const float* __restrict__ pl,
                                             const float* __restrict__ W1,
                                             const float* __restrict__ b1,
                                             const float* __restrict__ W2,
                                             const float* __restrict__ b2p) {
    __shared__ __align__(16) float sW1[128 * 64];
    __shared__ float sB1[128], sW2[128];
    const int tid  = threadIdx.x;
    const int lane = tid & 31;

    for (int i = tid * 4; i < 128 * 64; i += 256 * 4)
        *(float4*)&sW1[i] = *(const float4*)&W1[i];
    if (tid < 128) { sB1[tid] = __ldg(&b1[tid]); sW2[tid] = __ldg(&W2[tid]); }
    __syncthreads();

    const int   total = g_total;
    const float b2    = __ldg(b2p);

    for (int base = blockIdx.x * 256; base < total; base += NBLK_MLP * 256) {
        const int i  = base + tid;
        const int fi = (i < total) ? g_list[i] : -1;

        // gather 64 channels, packed as 32 f32x2 pairs (even, odd)
        uint64_t f2[32];
        if (fi >= 0) {
            const int bb = fi >> 16;
            const int p  = fi & 65535;
            const float* fp = feat + ((size_t)bb << 22) + p;   // b*64*65536
#pragma unroll
            for (int c = 0; c < 32; c++) {
                float fa = __ldg(fp + ((2 * c)     << 16));
                float fb = __ldg(fp + ((2 * c + 1) << 16));
                PACK_F32X2(f2[c], __float_as_uint(fa), __float_as_uint(fb));
            }
        } else {
#pragma unroll
            for (int c = 0; c < 32; c++) f2[c] = 0ull;
        }

        float score = b2;
#pragma unroll 2
        for (int k = 0; k < 128; k++) {
            uint64_t h2;
            PACK_F32X2(h2, __float_as_uint(sB1[k]), 0u);
            const ulonglong2* w2 = (const ulonglong2*)&sW1[k * 64];
#pragma unroll
            for (int c = 0; c < 16; c++) {
                ulonglong2 wp = w2[c];                 // LDS.128 broadcast
                FMA_F32X2(h2, wp.x, f2[2 * c],     h2);
                FMA_F32X2(h2, wp.y, f2[2 * c + 1], h2);
            }
            unsigned lo, hi;
            UNPACK_F32X2(lo, hi, h2);
            float h = __uint_as_float(lo) + __uint_as_float(hi);
            score = fmaf(sW2[k], fmaxf(h, 0.0f), score);
        }

        // per-batch sums with warp aggregation (warp is almost always batch-uniform)
        float e = 0.0f, pe = 0.0f;
        int bb = -1;
        if (fi >= 0) {
            e  = expf(score);    // |score| is O(1): no max-subtraction needed
            pe = e * __ldg(&pl[fi]);
            g_e[fi] = e;
            bb = fi >> 16;
        }
        unsigned act = __ballot_sync(0xffffffffu, fi >= 0);
        if (act) {
            int flead = __ffs(act) - 1;
            int b0 = __shfl_sync(0xffffffffu, bb, flead);
            bool uni = __all_sync(0xffffffffu, (fi < 0) || (bb == b0));
            if (uni) {
                float se = e, sp = pe;
#pragma unroll
                for (int off = 16; off; off >>= 1) {
                    se += __shfl_xor_sync(0xffffffffu, se, off);
                    sp += __shfl_xor_sync(0xffffffffu, sp, off);
                }
                if (lane == flead) {
                    atomicAdd(&g_sumE[b0],  se);
                    atomicAdd(&g_sumPE[b0], sp);
                }
            } else if (fi >= 0) {
                atomicAdd(&g_sumE[bb],  e);
                atomicAdd(&g_sumPE[bb], pe);
            }
        }
    }
}

// 4 pixels per thread; vector loads (aligned bases), scalar stores (out+1 is
// only 4B-aligned -> STG.128 would trap).
__global__ void k_maps(const int* __restrict__ zone,
                       const int* __restrict__ cats,
                       float* __restrict__ out_maps) {
    const int idx4 = (blockIdx.x * 256 + threadIdx.x) * 4;
    const int b    = idx4 >> 16;
    const int cat  = __ldg(&cats[b]);
    const bool has = g_cnt[b] > 0;
    const float inv = has ? (1.0f / g_sumE[b]) : 0.0f;
    int4   z = *(const int4*)&zone[idx4];
    float4 e = *(const float4*)&g_e[idx4];
    out_maps[idx4 + 0] = (has && z.x == cat) ? e.x * inv : 0.0f;
    out_maps[idx4 + 1] = (has && z.y == cat) ? e.y * inv : 0.0f;
    out_maps[idx4 + 2] = (has && z.z == cat) ? e.z * inv : 0.0f;
    out_maps[idx4 + 3] = (has && z.w == cat) ? e.w * inv : 0.0f;
}

__global__ void k_loss(const float* __restrict__ labels,
                       float* __restrict__ out, int write_loss) {
    const int t = threadIdx.x;   // 32 threads
    float x = 0.0f;
    if (g_cnt[t] > 0) x = g_sumPE[t] / g_sumE[t];
    const float y = labels[t];
    float term = fmaxf(x, 0.0f) - x * y + log1pf(expf(-fabsf(x)));
#pragma unroll
    for (int off = 16; off; off >>= 1)
        term += __shfl_xor_sync(0xffffffffu, term, off);
    if (t == 0 && write_loss) out[0] = term / 32.0f;
}

extern "C" void kernel_launch(void* const* d_in, const int* in_sizes, int n_in,
                              void* d_out, int out_size) {
    const float* pl     = (const float*)d_in[0];  // (B,1,H,W)
    const float* feat   = (const float*)d_in[1];  // (B,C,H,W)
    const int*   zone   = (const int*)  d_in[2];  // (B,H,W)
    const int*   cats   = (const int*)  d_in[3];  // (B,)
    const float* labels = (const float*)d_in[4];  // (B,)
    const float* W1     = (const float*)d_in[5];  // (128,64)
    const float* b1     = (const float*)d_in[6];  // (128,)
    const float* W2     = (const float*)d_in[7];  // (128,)
    const float* b2     = (const float*)d_in[8];  // ()
    float* out = (float*)d_out;

    const int nmap = NPIX;
    int map_off = out_size - nmap;
    if (map_off < 0) map_off = 0;

    k_init<<<1, 32>>>();
    k_compact<<<NPIX / 256, 256>>>(zone, cats);
    k_mlp<<<NBLK_MLP, 256>>>(feat, pl, W1, b1, W2, b2);
    k_maps<<<NPIX / 1024, 256>>>(zone, cats, out + map_off);
    k_loss<<<1, 32>>>(labels, out, map_off >= 1 ? 1 : 0);
}